// round 15
// baseline (speedup 1.0000x reference)
#include <cuda_runtime.h>

// PhotonicMesh: 512-port Clements mesh, 512 layers, 1024 batch rows.
// R15: packed fma.rn.f32x2 (FFMA2) on the R14 skeleton. R14 is at ~95% of
// the scalar FFMA pipe roofline, so the only remaining lever is halving
// FFMA pipe ops. Prior FFMA2 attempts failed from side-effects, all fixed:
//  - R4's port-packed state (u64 R[m] = (port 16t+m, port 16t+m+8)) - math
//    correctness proven in R4/R6.
//  - SLIM tables: 16B/pair ({ct,st} + {cos,sin} packed pairs); -st/-sin
//    derived via LOP3 XOR on the idle ALU pipe (no pre-negated copies).
//  - 1024 single-warp CTAs + __launch_bounds__(32,1): no barriers, no caps.
//  - Branchless odd-layer boundary (R14's SEL/identity trick).

#define N_PORT  512
#define N_LAYER 512
#define ATTEN_F 0.97723722095581054f   // sqrt(10^(-0.2/10))
#define SGN2    0x8000000080000000ULL

typedef unsigned long long u64;

// Tables: idx = (l*4 + m)*32 + lane; group covers pairs pA = 8*lane + m (lo)
// and pB = pA + 4 (hi) of layer l.
//   g_t0 = { pk(ctA,ctB)*ATTEN, pk(stA,stB)*ATTEN }
//   g_t1 = { pk(cosphiA,cosphiB), pk(sinphiA,sinphiB) }
__device__ ulonglong2 g_t0[N_LAYER * 4 * 32];
__device__ ulonglong2 g_t1[N_LAYER * 4 * 32];

__device__ __forceinline__ u64 pk(float lo, float hi) {
    u64 d; asm("mov.b64 %0, {%1, %2};" : "=l"(d) : "f"(lo), "f"(hi)); return d;
}
__device__ __forceinline__ void upk(u64 v, float& lo, float& hi) {
    asm("mov.b64 {%0, %1}, %2;" : "=f"(lo), "=f"(hi) : "l"(v));
}
__device__ __forceinline__ u64 fma2(u64 a, u64 b, u64 c) {
    u64 d; asm("fma.rn.f32x2 %0, %1, %2, %3;" : "=l"(d) : "l"(a), "l"(b), "l"(c));
    return d;
}
__device__ __forceinline__ u64 mul2(u64 a, u64 b) {
    u64 d; asm("mul.rn.f32x2 %0, %1, %2;" : "=l"(d) : "l"(a), "l"(b));
    return d;
}

__global__ void pm_coef_kernel(const float* __restrict__ thetas,
                               const float* __restrict__ phis,
                               const int*   __restrict__ mzi_idx) {
    int l    = blockIdx.x;
    int lane = threadIdx.x & 31;
    int m    = threadIdx.x >> 5;          // 0..3
    int pA = 8 * lane + m;
    int pB = pA + 4;
    bool odd = (l & 1) != 0;

    float ct[2] = {1.f, 1.f}, st[2] = {0.f, 0.f};
    float cp[2] = {1.f, 1.f}, sp[2] = {0.f, 0.f};
    int p[2] = {pA, pB};
    #pragma unroll
    for (int h = 0; h < 2; h++) {
        bool valid = (!odd) || (p[h] < 255);   // odd layers: 255 pairs
        if (valid) {
            int u = odd ? (2 * p[h] + 1) : (2 * p[h]);  // upper port
            int mi = mzi_idx[l * N_PORT + u];
            float s_, c_;
            sincosf(thetas[mi], &s_, &c_);
            ct[h] = c_ * ATTEN_F;  st[h] = s_ * ATTEN_F;
            sincosf(phis[mi], &s_, &c_);
            cp[h] = c_;  sp[h] = s_;
        }
    }
    int idx = (l * 4 + m) * 32 + lane;
    g_t0[idx] = make_ulonglong2(pk(ct[0], ct[1]), pk(st[0], st[1]));
    g_t1[idx] = make_ulonglong2(pk(cp[0], cp[1]), pk(sp[0], sp[1]));
}

struct Grp { u64 ct, st, er, ei; };
struct CoefBlk { Grp e[4]; Grp o[4]; };   // even layer + odd layer groups

__device__ __forceinline__ void load_coefs(CoefBlk& b, int l, int lane) {
    #pragma unroll
    for (int m = 0; m < 4; m++) {
        int idx = (l * 4 + m) * 32 + lane;
        ulonglong2 a = __ldg(&g_t0[idx]);
        ulonglong2 c = __ldg(&g_t1[idx]);
        b.e[m].ct = a.x; b.e[m].st = a.y; b.e[m].er = c.x; b.e[m].ei = c.y;
    }
    #pragma unroll
    for (int m = 0; m < 4; m++) {
        int idx = ((l + 1) * 4 + m) * 32 + lane;
        ulonglong2 a = __ldg(&g_t0[idx]);
        ulonglong2 c = __ldg(&g_t1[idx]);
        b.o[m].ct = a.x; b.o[m].st = a.y; b.o[m].er = c.x; b.o[m].ei = c.y;
    }
}

// Packed butterfly on two independent MZIs (lo = pair pA, hi = pair pB):
//   u = ct*xi + st*xj ; xj' = ct*xj - st*xi ; xi' = e^{i phi} * u
__device__ __forceinline__ void bfly2(u64& Ri, u64& Ii, u64& Rj, u64& Ij,
                                      const Grp& c) {
    u64 nst = c.st ^ SGN2;    // LOP3 on the idle ALU pipe
    u64 nei = c.ei ^ SGN2;
    u64 ur = fma2(c.ct, Ri, mul2(c.st, Rj));
    u64 ui = fma2(c.ct, Ii, mul2(c.st, Ij));
    u64 vr = fma2(c.ct, Rj, mul2(nst, Ri));
    u64 vi = fma2(c.ct, Ij, mul2(nst, Ii));
    Ri = fma2(c.er, ur, mul2(nei, ui));
    Ii = fma2(c.er, ui, mul2(c.ei, ur));
    Rj = vr;  Ij = vi;
}

// Two layers (even l, odd l+1), branch-free.
__device__ __forceinline__ void step2(u64* R, u64* I, const CoefBlk& b,
                                      int lane) {
    // ---- EVEN layer: groups (R[2m], R[2m+1]) ----
    #pragma unroll
    for (int m = 0; m < 4; m++)
        bfly2(R[2 * m], I[2 * m], R[2 * m + 1], I[2 * m + 1], b.e[m]);

    // ---- ODD layer boundary snapshots (post-even) ----
    float x0r, x8r, x0i, x8i, x7r, x15r, x7i, x15i;
    upk(R[0], x0r, x8r);  upk(I[0], x0i, x8i);
    upk(R[7], x7r, x15r); upk(I[7], x7i, x15i);
    float nx0r  = __shfl_down_sync(0xffffffffu, x0r, 1);   // next lane x0
    float nx0i  = __shfl_down_sync(0xffffffffu, x0i, 1);
    float px15r = __shfl_up_sync  (0xffffffffu, x15r, 1);  // prev lane x15
    float px15i = __shfl_up_sync  (0xffffffffu, x15i, 1);
    // cross-pair lower coefficient: (lane-1's pair 8(lane-1)+7 ct/st, own
    // group-3 lo ct/st); identity at lane 0 via SELs (global port 0 pass)
    float ct3lo, ct3hi, st3lo, st3hi;
    upk(b.o[3].ct, ct3lo, ct3hi);
    upk(b.o[3].st, st3lo, st3hi);
    float ctp = __shfl_up_sync(0xffffffffu, ct3hi, 1);
    float stp = __shfl_up_sync(0xffffffffu, st3hi, 1);
    ctp = (lane > 0) ? ctp : 1.0f;
    stp = (lane > 0) ? stp : 0.0f;
    u64 xjr   = pk(x8r,  nx0r);           // upper partner (x8, next x0)
    u64 xji   = pk(x8i,  nx0i);
    u64 lowbr = pk(px15r, x7r);           // lower partner (prev x15, x7)
    u64 lowbi = pk(px15i, x7i);
    u64 ct2l  = pk(ctp, ct3lo);
    u64 nst2l = pk(stp, st3lo) ^ SGN2;

    // ---- ODD local groups (R[2m+1], R[2m+2]), m = 0..2 ----
    bfly2(R[1], I[1], R[2], I[2], b.o[0]);
    bfly2(R[3], I[3], R[4], I[4], b.o[1]);
    bfly2(R[5], I[5], R[6], I[6], b.o[2]);

    // ---- leftover upper ports (x7, x15): phase applies; lane31-hi is the
    //      identity pair 255 => exact passthrough (shfl garbage x st=0) ----
    {
        u64 nei = b.o[3].ei ^ SGN2;
        u64 ur = fma2(b.o[3].ct, R[7], mul2(b.o[3].st, xjr));
        u64 ui = fma2(b.o[3].ct, I[7], mul2(b.o[3].st, xji));
        R[7] = fma2(b.o[3].er, ur, mul2(nei, ui));
        I[7] = fma2(b.o[3].er, ui, mul2(b.o[3].ei, ur));
    }
    // ---- leftover lower ports (x0, x8): real coefficients; lane0-lo is
    //      identity via SELs (shfl garbage x -0 = exact 0) ----
    R[0] = fma2(ct2l, R[0], mul2(nst2l, lowbr));
    I[0] = fma2(ct2l, I[0], mul2(nst2l, lowbi));
}

__global__ __launch_bounds__(32, 1)
void pm_mesh_kernel(const float* __restrict__ x, float* __restrict__ out) {
    const int lane = threadIdx.x & 31;
    const int row  = blockIdx.x;          // one warp-CTA per batch row

    u64 R[8], I[8];   // R[m] = (re port 16*lane+m, re port 16*lane+m+8)

    // ---- load input (real), imag = 0, into packed layout ----
    {
        const float4* x4 = reinterpret_cast<const float4*>(x);
        float t[16];
        #pragma unroll
        for (int v = 0; v < 4; v++) {
            float4 q = x4[(size_t)row * (N_PORT / 4) + lane * 4 + v];
            t[4 * v + 0] = q.x; t[4 * v + 1] = q.y;
            t[4 * v + 2] = q.z; t[4 * v + 3] = q.w;
        }
        #pragma unroll
        for (int m = 0; m < 8; m++) { R[m] = pk(t[m], t[m + 8]); I[m] = 0ull; }
    }

    // ---- software-pipelined propagation: ping-pong coefficient buffers ----
    CoefBlk A, B;
    load_coefs(A, 0, lane);

    #pragma unroll 1
    for (int l = 0; l < N_LAYER; l += 4) {
        int ln1 = min(l + 2, N_LAYER - 2);   // tail clamp (result unused)
        load_coefs(B, ln1, lane);
        step2(R, I, A, lane);

        int ln2 = min(l + 4, N_LAYER - 2);   // tail clamp (result unused)
        load_coefs(A, ln2, lane);
        step2(R, I, B, lane);
    }

    // ---- square-law detection + store ----
    {
        float pr[16];
        #pragma unroll
        for (int m = 0; m < 8; m++) {
            float rl, rh, il, ih;
            upk(R[m], rl, rh);  upk(I[m], il, ih);
            pr[m]     = rl * rl + il * il;
            pr[m + 8] = rh * rh + ih * ih;
        }
        float4* o4 = reinterpret_cast<float4*>(out);
        #pragma unroll
        for (int v = 0; v < 4; v++) {
            float4 q;
            q.x = pr[4 * v + 0]; q.y = pr[4 * v + 1];
            q.z = pr[4 * v + 2]; q.w = pr[4 * v + 3];
            o4[(size_t)row * (N_PORT / 4) + lane * 4 + v] = q;
        }
    }
}

extern "C" void kernel_launch(void* const* d_in, const int* in_sizes, int n_in,
                              void* d_out, int out_size) {
    const float* x       = (const float*)d_in[0];
    const float* thetas  = (const float*)d_in[1];
    const float* phis    = (const float*)d_in[2];
    // d_in[3] = partner (unused: structure is static)
    const int*   mzi_idx = (const int*)d_in[4];
    // d_in[5] = role (unused: structure is static)
    float* out = (float*)d_out;

    pm_coef_kernel<<<N_LAYER, 128>>>(thetas, phis, mzi_idx);
    // 1024 single-warp CTAs: spread across ALL SMs (~7 per SM on 148+ SMs)
    pm_mesh_kernel<<<1024, 32>>>(x, out);
}